// round 5
// baseline (speedup 1.0000x reference)
#include <cuda_runtime.h>
#include <math.h>

#define BB 64
#define NN 128

// scratch for intermediate coors/vel between layers (no allocs allowed)
__device__ float g_c0[BB*NN*2];
__device__ float g_v0[BB*NN*2];
__device__ float g_c1[BB*NN*2];
__device__ float g_v1[BB*NN*2];

union F2U { float2 f; unsigned long long u; };

__device__ __forceinline__ float2 ffma2(float2 a, float2 b, float2 c) {
    F2U A, B, C, R;
    A.f = a; B.f = b; C.f = c;
    asm("fma.rn.f32x2 %0, %1, %2, %3;" : "=l"(R.u) : "l"(A.u), "l"(B.u), "l"(C.u));
    return R.f;
}
__device__ __forceinline__ float2 fmul2(float2 a, float2 b) {
    F2U A, B, R;
    A.f = a; B.f = b;
    asm("mul.rn.f32x2 %0, %1, %2;" : "=l"(R.u) : "l"(A.u), "l"(B.u));
    return R.f;
}

__device__ __forceinline__ float tanhaf(float x) {
    float r; asm("tanh.approx.f32 %0, %1;" : "=f"(r) : "f"(x)); return r;
}

// input h = x/2 (accumulated with pre-scaled weights). returns silu(x) = h + h*tanh(h).
__device__ __forceinline__ float2 silu2_pre(float2 h) {
    float t0 = tanhaf(h.x);
    float t1 = tanhaf(h.y);
    return ffma2(h, make_float2(t0, t1), h);
}
// plain silu on x
__device__ __forceinline__ float2 silu2(float2 x) {
    float2 h = fmul2(x, make_float2(0.5f, 0.5f));
    return silu2_pre(h);
}

__device__ __forceinline__ float seluf(float x) {
    const float scale = 1.0507009873554805f;
    const float alpha = 1.6732632423543772f;
    return x > 0.0f ? scale * x : scale * alpha * expm1f(x);
}

__global__ __launch_bounds__(128, 5)
void egnn_layer_kernel(const float* __restrict__ t,
                       const float* __restrict__ cin,
                       const float* __restrict__ vin,
                       float* __restrict__ cout,
                       float* __restrict__ vout,
                       const float* __restrict__ We1,
                       const float* __restrict__ be1,
                       const float* __restrict__ We2,
                       const float* __restrict__ be2,
                       const float* __restrict__ Wc1,
                       const float* __restrict__ bc1,
                       const float* __restrict__ Wc2,
                       const float* __restrict__ bc2,
                       const float* __restrict__ Wv,
                       const float* __restrict__ bv,
                       int l)
{
    // block = (batch, 4 i's). warp w owns i = ibase + w.
    // each thread handles 4 edges for its i: packed pairs A=(ln, ln+32), B=(ln+64, ln+96).
    __shared__ float4 sUV[16];      // {u,u,v,v}  (x0.5)
    __shared__ float4 sWC[16];      // {w,w,c,c}  (x0.5, c includes be1)
    __shared__ float2 sbe2[16];     // dup be2    (x0.5)
    __shared__ float4 sWe2d[128];   // We2 dup pairs (x0.5)
    __shared__ float4 sWc1d[512];   // Wc1 dup pairs (x0.5)
    __shared__ float2 sbc1d[64];    // dup bc1    (x0.5)
    __shared__ float4 sWc2d[32];    // dup Wc2 pairs (unscaled)
    __shared__ float2 scj2[NN];
    __shared__ float  stj[NN];

    const int tid   = threadIdx.x;
    const int wid   = tid >> 5;
    const int ln    = tid & 31;
    const int bb    = blockIdx.x >> 5;
    const int ibase = (blockIdx.x & 31) * 4;
    const int i     = ibase + wid;

    // ---- setup: fold + duplicate + prescale weights into shared ----
    const float* we1 = We1 + l * 128;
    if (tid < 16) {
        float u = 0.5f * (we1[tid] + we1[16 + tid] + we1[32 + tid]);
        float v = 0.5f * (we1[48 + tid] + we1[64 + tid] + we1[80 + tid]);
        float w = 0.5f * we1[96 + tid];
        float c = 0.5f * (we1[112 + tid] + be1[l * 16 + tid]);
        sUV[tid] = make_float4(u, u, v, v);
        sWC[tid] = make_float4(w, w, c, c);
        float b2 = 0.5f * be2[l * 16 + tid];
        sbe2[tid] = make_float2(b2, b2);
    } else if (tid < 80) {
        int k = tid - 16;
        float b = 0.5f * bc1[l * 64 + k];
        sbc1d[k] = make_float2(b, b);
    } else if (tid < 112) {
        int k = tid - 80;
        float a = Wc2[l * 64 + 2 * k];
        float b = Wc2[l * 64 + 2 * k + 1];
        sWc2d[k] = make_float4(a, a, b, b);
    }
    {
        int n = tid >> 3, c = tid & 7;
        float a = 0.5f * We2[l * 256 + n * 16 + 2 * c];
        float b = 0.5f * We2[l * 256 + n * 16 + 2 * c + 1];
        sWe2d[tid] = make_float4(a, a, b, b);
    }
    #pragma unroll
    for (int idx = tid; idx < 512; idx += 128) {
        int n = idx >> 5, c = idx & 31;
        float a = 0.5f * Wc1[l * 1024 + n * 64 + 2 * c];
        float b = 0.5f * Wc1[l * 1024 + n * 64 + 2 * c + 1];
        sWc1d[idx] = make_float4(a, a, b, b);
    }
    {
        const float2* c2 = (const float2*)(cin + bb * NN * 2);
        scj2[tid] = c2[tid];            // 128 threads, 128 nodes
        stj[tid]  = t[bb * NN + tid];
    }
    __syncthreads();

    const float ti   = stj[i];
    const float2 ci  = scj2[i];
    const float2 ti2 = make_float2(ti, ti);

    // ---- per-pair: layer1 + MLP2 -> q (sequential to bound registers) ----
    float2 q_a[16], q_b[16];
    #pragma unroll
    for (int pp = 0; pp < 2; ++pp) {
        const int j0 = ln + (pp ? 64 : 0);
        const int j1 = j0 + 32;
        float2* q = pp ? q_b : q_a;

        const float2 cj0 = scj2[j0];
        const float2 cj1 = scj2[j1];
        const float2 tj2 = make_float2(stj[j0], stj[j1]);
        const float2 dx2 = make_float2(ci.x - cj0.x, ci.x - cj1.x);
        const float2 dy2 = make_float2(ci.y - cj0.y, ci.y - cj1.y);
        const float2 d2  = ffma2(dx2, dx2, fmul2(dy2, dy2));

        float2 x1[16];
        #pragma unroll
        for (int k = 0; k < 16; ++k) {
            float4 uv = sUV[k];
            float4 wc = sWC[k];
            // h = z/2 directly (weights pre-scaled)
            float2 h = ffma2(ti2, make_float2(uv.x, uv.y),
                      ffma2(tj2, make_float2(uv.z, uv.w),
                      ffma2(d2,  make_float2(wc.x, wc.y),
                                 make_float2(wc.z, wc.w))));
            x1[k] = silu2_pre(h);
        }
        #pragma unroll
        for (int c = 0; c < 8; ++c) {
            float2 a0 = sbe2[2 * c];
            float2 a1 = sbe2[2 * c + 1];
            #pragma unroll
            for (int n = 0; n < 16; ++n) {
                float4 w = sWe2d[n * 8 + c];
                a0 = ffma2(x1[n], make_float2(w.x, w.y), a0);
                a1 = ffma2(x1[n], make_float2(w.z, w.w), a1);
            }
            // a0 = m/2 -> silu(m) -> outer silu
            q[2 * c]     = silu2(silu2_pre(a0));
            q[2 * c + 1] = silu2(silu2_pre(a1));
        }
    }

    // ---- MLP3 joint over both pairs: weight LDS amortized x4 edges ----
    const float bc2l = bc2[l];
    float2 wsa = make_float2(bc2l, bc2l);
    float2 wsb = make_float2(bc2l, bc2l);
    #pragma unroll 4
    for (int c = 0; c < 32; ++c) {
        float2 bi0 = sbc1d[2 * c];
        float2 bi1 = sbc1d[2 * c + 1];
        float2 aa0 = bi0, aa1 = bi1;
        float2 ba0 = bi0, ba1 = bi1;
        #pragma unroll
        for (int n = 0; n < 16; ++n) {
            float4 w = sWc1d[n * 32 + c];
            float2 wlo = make_float2(w.x, w.y);
            float2 whi = make_float2(w.z, w.w);
            aa0 = ffma2(q_a[n], wlo, aa0);
            aa1 = ffma2(q_a[n], whi, aa1);
            ba0 = ffma2(q_b[n], wlo, ba0);
            ba1 = ffma2(q_b[n], whi, ba1);
        }
        float4 wc2 = sWc2d[c];
        float2 w0 = make_float2(wc2.x, wc2.y);
        float2 w1 = make_float2(wc2.z, wc2.w);
        wsa = ffma2(silu2_pre(aa0), w0, wsa);
        wsa = ffma2(silu2_pre(aa1), w1, wsa);
        wsb = ffma2(silu2_pre(ba0), w0, wsb);
        wsb = ffma2(silu2_pre(ba1), w1, wsb);
    }

    // ---- agg: recompute rel coords (cheap LDS), accumulate, warp-reduce ----
    float ax, ay;
    {
        const float2 cj0 = scj2[ln];
        const float2 cj1 = scj2[ln + 32];
        const float2 cj2 = scj2[ln + 64];
        const float2 cj3 = scj2[ln + 96];
        float2 dxa = make_float2(ci.x - cj0.x, ci.x - cj1.x);
        float2 dya = make_float2(ci.y - cj0.y, ci.y - cj1.y);
        float2 dxb = make_float2(ci.x - cj2.x, ci.x - cj3.x);
        float2 dyb = make_float2(ci.y - cj2.y, ci.y - cj3.y);
        float2 ax2 = ffma2(wsb, dxb, fmul2(wsa, dxa));
        float2 ay2 = ffma2(wsb, dyb, fmul2(wsa, dya));
        ax = ax2.x + ax2.y;
        ay = ay2.x + ay2.y;
    }
    #pragma unroll
    for (int off = 16; off > 0; off >>= 1) {
        ax += __shfl_down_sync(0xFFFFFFFFu, ax, off);
        ay += __shfl_down_sync(0xFFFFFFFFu, ay, off);
    }

    if (ln == 0) {
        float wv  = Wv[l * 3] + Wv[l * 3 + 1] + Wv[l * 3 + 2];
        float phi = fmaf(ti, wv, bv[l]);
        float vx = vin[(bb * NN + i) * 2];
        float vy = vin[(bb * NN + i) * 2 + 1];
        float nvx = fmaf(phi, vx, ax);
        float nvy = fmaf(phi, vy, ay);
        float ncx = ci.x + nvx;
        float ncy = ci.y + nvy;
        cout[(bb * NN + i) * 2]     = seluf(ncx);
        cout[(bb * NN + i) * 2 + 1] = seluf(ncy);
        vout[(bb * NN + i) * 2]     = seluf(nvx);
        vout[(bb * NN + i) * 2 + 1] = seluf(nvy);
    }
}

__global__ void egnn_head_kernel(const float* __restrict__ cin,
                                 const float* __restrict__ vin,
                                 const float* __restrict__ Wconv1,
                                 const float* __restrict__ bconv1,
                                 const float* __restrict__ Wconv2,
                                 const float* __restrict__ bconv2,
                                 float* __restrict__ out)
{
    int idx = blockIdx.x * blockDim.x + threadIdx.x;
    if (idx >= BB * NN) return;

    float x0 = seluf(cin[idx * 2]);
    float x1 = seluf(cin[idx * 2 + 1]);
    float x2 = seluf(vin[idx * 2]);
    float x3 = seluf(vin[idx * 2 + 1]);

    float y0 = bconv2[0], y1 = bconv2[1], y2 = bconv2[2], y3 = bconv2[3];
    #pragma unroll
    for (int o = 0; o < 32; o++) {
        float h = bconv1[o];
        h = fmaf(x0, Wconv1[o * 4 + 0], h);
        h = fmaf(x1, Wconv1[o * 4 + 1], h);
        h = fmaf(x2, Wconv1[o * 4 + 2], h);
        h = fmaf(x3, Wconv1[o * 4 + 3], h);
        h = seluf(h);
        y0 = fmaf(h, Wconv2[0 * 32 + o], y0);
        y1 = fmaf(h, Wconv2[1 * 32 + o], y1);
        y2 = fmaf(h, Wconv2[2 * 32 + o], y2);
        y3 = fmaf(h, Wconv2[3 * 32 + o], y3);
    }
    out[idx * 2]                   = y0;
    out[idx * 2 + 1]               = y1;
    out[BB * NN * 2 + idx * 2]     = y2;
    out[BB * NN * 2 + idx * 2 + 1] = y3;
}

extern "C" void kernel_launch(void* const* d_in, const int* in_sizes, int n_in,
                              void* d_out, int out_size)
{
    const float* t      = (const float*)d_in[0];
    const float* coors  = (const float*)d_in[1];
    const float* vel    = (const float*)d_in[2];
    const float* We1    = (const float*)d_in[3];
    const float* be1    = (const float*)d_in[4];
    const float* We2    = (const float*)d_in[5];
    const float* be2    = (const float*)d_in[6];
    const float* Wc1    = (const float*)d_in[7];
    const float* bc1    = (const float*)d_in[8];
    const float* Wc2    = (const float*)d_in[9];
    const float* bc2    = (const float*)d_in[10];
    const float* Wv     = (const float*)d_in[11];
    const float* bv     = (const float*)d_in[12];
    const float* Wconv1 = (const float*)d_in[13];
    const float* bconv1 = (const float*)d_in[14];
    const float* Wconv2 = (const float*)d_in[15];
    const float* bconv2 = (const float*)d_in[16];
    float* out = (float*)d_out;

    float *c0, *v0, *c1, *v1;
    cudaGetSymbolAddress((void**)&c0, g_c0);
    cudaGetSymbolAddress((void**)&v0, g_v0);
    cudaGetSymbolAddress((void**)&c1, g_c1);
    cudaGetSymbolAddress((void**)&v1, g_v1);

    dim3 grid(BB * 32);   // 2048 blocks: (batch, group of 4 i's), warp-per-i
    dim3 blk(128);
    egnn_layer_kernel<<<grid, blk>>>(t, coors, vel, c0, v0,
                                     We1, be1, We2, be2, Wc1, bc1, Wc2, bc2,
                                     Wv, bv, 0);
    egnn_layer_kernel<<<grid, blk>>>(t, c0, v0, c1, v1,
                                     We1, be1, We2, be2, Wc1, bc1, Wc2, bc2,
                                     Wv, bv, 1);
    egnn_head_kernel<<<(BB * NN + 127) / 128, 128>>>(c1, v1, Wconv1, bconv1,
                                                     Wconv2, bconv2, out);
}